// round 6
// baseline (speedup 1.0000x reference)
#include <cuda_runtime.h>
#include <cstdint>

// Problem dims
#define SEQ  512
#define BAT  64
#define INP  512
#define HID  1024
#define OUTD 512
#define BH   (64LL * 1024)   // elements per timestep slice of U / Hall (BAT*HID)

// ---------------- static device scratch (allocations are forbidden) ----------------
__device__ float g_U   [SEQ * BAT * HID];          // u_t = x_t @ Wxh^T + b_i2h
__device__ float g_Hall[(SEQ + 1) * BAT * HID];    // h_t, t = 0..512
__device__ float g_P0  [2048 * HID];               // block-local prefix (ping)
__device__ float g_P1  [2048 * HID];               // (pong)
__device__ float g_Wa  [HID * HID];                // Whh^2 / Whh^8
__device__ float g_Wb  [HID * HID];                // Whh^4 / Whh^16
__device__ float g_part[16 * BAT * HID];           // split-K partials (boundary)
__device__ float g_OUT [SEQ * BAT * OUTD];         // out_t

// ---------------- GEMM: C[r][n] = sum_k A(r,k) * B(n,k) (+bias)(+Add) ----------------
// Row addressing supports block-scatter: addr(r) = base + (r>>6)*Outer + (r&63)*Inner.
struct GP {
    const float* A; long long aO, aI; int M;       // M = real row count (clamped loads)
    const float* W; long long wn, wk;              // B(n,k) = W[n*wn + k*wk]; wk==1 -> NT
    const float* bias;                             // nullable, indexed by global n
    const float* Add; long long adO, adI;          // nullable, same row mapping as C
    float* C; long long cO, cI;
    int K, N;                                      // K is per-z when gridDim.z > 1
    float* part; long long partStride;             // split-K output: part + z*stride, ld N
};

__device__ __forceinline__ unsigned long long dup2f(float v) {
    unsigned u = __float_as_uint(v);
    unsigned long long d;
    asm("mov.b64 %0, {%1, %1};" : "=l"(d) : "r"(u));
    return d;
}
__device__ __forceinline__ void fma2(unsigned long long& d, unsigned long long a, unsigned long long b) {
    asm("fma.rn.f32x2 %0, %1, %2, %0;" : "+l"(d) : "l"(a), "l"(b));
}

__global__ __launch_bounds__(256, 1) void k_gemm(GP g) {
    __shared__ float As[2][16][128];   // [k][m]
    __shared__ float Bs[2][16][128];   // [k][n]
    const int tid = threadIdx.x;
    const int tx = tid & 15, ty = tid >> 4;          // 16 x 16 threads, 8x8 microtile
    const long long n0 = (long long)blockIdx.x * 128;
    const int mbase = blockIdx.y * 128;
    const int z = blockIdx.z;
    const bool split = (gridDim.z > 1);
    const bool wk1 = (g.wk == 1);

    const float* Abase = g.A + (split ? (long long)z * g.K : 0);   // A is k-contiguous
    const float* Wbase = g.W + (split ? (long long)z * g.K * g.wk : 0);

    // per-thread gmem assignments: 2 float4 for A, 2 float4 for B per k-tile
    const float* ap[2]; int am[2], akq[2];
    const float* bp[2]; int bi0[2], bi1[2];
    #pragma unroll
    for (int q = 0; q < 2; q++) {
        int s = tid * 2 + q;
        am[q] = s >> 2; akq[q] = s & 3;
        int mm = mbase + am[q]; if (mm > g.M - 1) mm = g.M - 1;   // clamp (M=64 case)
        ap[q] = Abase + (long long)(mm >> 6) * g.aO + (long long)(mm & 63) * g.aI + akq[q] * 4;
        if (wk1) {            // NT: k contiguous in W
            bi0[q] = s >> 2;  // n (0..127)
            bi1[q] = s & 3;   // k-quad
            bp[q] = Wbase + (n0 + bi0[q]) * g.wn + bi1[q] * 4;
        } else {              // NN: n contiguous in W
            bi0[q] = s >> 5;  // k (0..15)
            bi1[q] = s & 31;  // n-quad
            bp[q] = Wbase + (long long)bi0[q] * g.wk + n0 + bi1[q] * 4;
        }
    }

    unsigned long long acc[8][4];
    #pragma unroll
    for (int i = 0; i < 8; i++)
        #pragma unroll
        for (int j = 0; j < 4; j++) acc[i][j] = 0ull;

    const int nIter = g.K >> 4;
    float4 va[2], vb[2];

    auto loadT = [&](int k0) {
        #pragma unroll
        for (int q = 0; q < 2; q++) va[q] = *(const float4*)(ap[q] + k0);
        if (wk1) {
            #pragma unroll
            for (int q = 0; q < 2; q++) vb[q] = *(const float4*)(bp[q] + k0);
        } else {
            #pragma unroll
            for (int q = 0; q < 2; q++) vb[q] = *(const float4*)(bp[q] + (long long)k0 * g.wk);
        }
    };
    auto storeT = [&](int buf) {
        #pragma unroll
        for (int q = 0; q < 2; q++) {
            As[buf][akq[q]*4+0][am[q]] = va[q].x;
            As[buf][akq[q]*4+1][am[q]] = va[q].y;
            As[buf][akq[q]*4+2][am[q]] = va[q].z;
            As[buf][akq[q]*4+3][am[q]] = va[q].w;
            if (wk1) {
                Bs[buf][bi1[q]*4+0][bi0[q]] = vb[q].x;
                Bs[buf][bi1[q]*4+1][bi0[q]] = vb[q].y;
                Bs[buf][bi1[q]*4+2][bi0[q]] = vb[q].z;
                Bs[buf][bi1[q]*4+3][bi0[q]] = vb[q].w;
            } else {
                *(float4*)&Bs[buf][bi0[q]][bi1[q]*4] = vb[q];
            }
        }
    };

    loadT(0); storeT(0);
    __syncthreads();

    for (int it = 0; it < nIter; it++) {
        const int cur = it & 1;
        const bool pf = (it + 1 < nIter);
        if (pf) loadT((it + 1) << 4);
        #pragma unroll
        for (int k = 0; k < 16; k++) {
            float4 a0 = *(const float4*)&As[cur][k][ty*8];
            float4 a1 = *(const float4*)&As[cur][k][ty*8 + 4];
            ulonglong2 b0 = *(const ulonglong2*)&Bs[cur][k][tx*8];
            ulonglong2 b1 = *(const ulonglong2*)&Bs[cur][k][tx*8 + 4];
            unsigned long long ad[8];
            ad[0] = dup2f(a0.x); ad[1] = dup2f(a0.y); ad[2] = dup2f(a0.z); ad[3] = dup2f(a0.w);
            ad[4] = dup2f(a1.x); ad[5] = dup2f(a1.y); ad[6] = dup2f(a1.z); ad[7] = dup2f(a1.w);
            unsigned long long bv[4] = {b0.x, b0.y, b1.x, b1.y};
            #pragma unroll
            for (int i = 0; i < 8; i++)
                #pragma unroll
                for (int j = 0; j < 4; j++) fma2(acc[i][j], ad[i], bv[j]);
        }
        if (pf) storeT(cur ^ 1);
        __syncthreads();
    }

    if (split) {
        float* P = g.part + (long long)z * g.partStride;
        #pragma unroll
        for (int i = 0; i < 8; i++) {
            int r = mbase + ty*8 + i;
            if (r < g.M) {
                #pragma unroll
                for (int j = 0; j < 4; j++) {
                    float2 v;
                    v.x = __uint_as_float((unsigned)(acc[i][j]));
                    v.y = __uint_as_float((unsigned)(acc[i][j] >> 32));
                    *(float2*)(P + (long long)r * g.N + n0 + tx*8 + j*2) = v;
                }
            }
        }
    } else {
        #pragma unroll
        for (int i = 0; i < 8; i++) {
            int r = mbase + ty*8 + i;
            if (r < g.M) {
                long long ro = (long long)(r >> 6) * g.cO + (long long)(r & 63) * g.cI;
                #pragma unroll
                for (int j = 0; j < 4; j++) {
                    long long n = n0 + tx*8 + j*2;
                    float2 v;
                    v.x = __uint_as_float((unsigned)(acc[i][j]));
                    v.y = __uint_as_float((unsigned)(acc[i][j] >> 32));
                    if (g.bias) { v.x += g.bias[n]; v.y += g.bias[n + 1]; }
                    if (g.Add) {
                        const float* adp = g.Add + (long long)(r >> 6) * g.adO
                                         + (long long)(r & 63) * g.adI + n;
                        v.x += adp[0]; v.y += adp[1];
                    }
                    *(float2*)(g.C + ro + n) = v;
                }
            }
        }
    }
}

// ---------------- small helpers ----------------
// P0[g][n] = U[16*(g/64)][g%64][n]  (p_{j,1} = u_{16j})
__global__ void k_initP(float* P, const float* U) {
    long long gI = blockIdx.x; int n = threadIdx.x;
    P[gI * 1024 + n] = U[(gI >> 6) * (16 * BH) + (gI & 63) * 1024 + n];
}
__global__ void k_zero(float* p) { p[(long long)blockIdx.x * 1024 + threadIdx.x] = 0.f; }

// dst[i] = p[i] + sum_z part[z][i], i < 65536, Z = 16
__global__ void k_reduce(float* dst, const float* p, const float* part) {
    long long i = (long long)blockIdx.x * 1024 + threadIdx.x;
    float s = p[i];
    #pragma unroll
    for (int z = 0; z < 16; z++) s += part[(long long)z * BH + i];
    dst[i] = s;
}

// y = logits * mask; y -= logsumexp(y). One warp per 512-wide row.
__global__ void k_logsm(float* io, const float* mask) {
    int row  = blockIdx.x * 8 + (threadIdx.x >> 5);
    int lane = threadIdx.x & 31;
    long long base = (long long)row * OUTD + lane;
    float v[16]; float mx = -1e30f;
    #pragma unroll
    for (int i = 0; i < 16; i++) {
        v[i] = io[base + 32 * i] * mask[base + 32 * i];
        mx = fmaxf(mx, v[i]);
    }
    #pragma unroll
    for (int o = 16; o > 0; o >>= 1) mx = fmaxf(mx, __shfl_xor_sync(0xffffffffu, mx, o));
    float s = 0.f;
    #pragma unroll
    for (int i = 0; i < 16; i++) s += expf(v[i] - mx);
    #pragma unroll
    for (int o = 16; o > 0; o >>= 1) s += __shfl_xor_sync(0xffffffffu, s, o);
    float lse = mx + logf(s);
    #pragma unroll
    for (int i = 0; i < 16; i++) io[base + 32 * i] = v[i] - lse;
}

// ---------------- host orchestration ----------------
static inline void launch_g(const float* A, long long aO, long long aI, int M,
                            const float* W, long long wn, long long wk,
                            const float* bias,
                            const float* Add, long long adO, long long adI,
                            float* C, long long cO, long long cI,
                            int K, int N, int Z, float* part)
{
    GP g;
    g.A = A; g.aO = aO; g.aI = aI; g.M = M;
    g.W = W; g.wn = wn; g.wk = wk;
    g.bias = bias; g.Add = Add; g.adO = adO; g.adI = adI;
    g.C = C; g.cO = cO; g.cI = cI;
    g.K = (Z > 1) ? (K / Z) : K; g.N = N;
    g.part = part; g.partStride = BH;
    dim3 grid(N / 128, (M + 127) / 128, Z);
    k_gemm<<<grid, 256>>>(g);
}

extern "C" void kernel_launch(void* const* d_in, const int* in_sizes, int n_in,
                              void* d_out, int out_size)
{
    const float* x    = (const float*)d_in[0];   // [512,64,512]
    const float* mask = (const float*)d_in[1];   // [512,64,512]
    const float* Wi2h = (const float*)d_in[2];   // [1024,1536]
    const float* bi2h = (const float*)d_in[3];   // [1024]
    const float* Wi2o = (const float*)d_in[4];   // [512,1536]
    const float* bi2o = (const float*)d_in[5];   // [512]
    const float* Wo2o = (const float*)d_in[6];   // [512,1536]
    const float* bo2o = (const float*)d_in[7];   // [512]
    float* out = (float*)d_out;                  // [512,64,512] log-probs
    (void)in_sizes; (void)n_in; (void)out_size;

    float *U, *Hall, *P0, *P1, *Wa, *Wb, *part, *OUTb;
    cudaGetSymbolAddress((void**)&U,    g_U);
    cudaGetSymbolAddress((void**)&Hall, g_Hall);
    cudaGetSymbolAddress((void**)&P0,   g_P0);
    cudaGetSymbolAddress((void**)&P1,   g_P1);
    cudaGetSymbolAddress((void**)&Wa,   g_Wa);
    cudaGetSymbolAddress((void**)&Wb,   g_Wb);
    cudaGetSymbolAddress((void**)&part, g_part);
    cudaGetSymbolAddress((void**)&OUTb, g_OUT);

    const float* Whh = Wi2h + 512;   // [1024,1024] slice, row stride 1536

    // 1) U = X @ Wxh^T + b_i2h   (M=32768, N=1024, K=512)
    launch_g(x, 64 * 512, 512, SEQ * BAT, Wi2h, 1536, 1, bi2h,
             nullptr, 0, 0, U, BH, 1024, 512, 1024, 1, nullptr);

    // 2) W16 = Whh^16 via 4 squarings (C = A @ B, B in NN layout: wn=1)
    launch_g(Whh, 64 * 1536, 1536, 1024, Whh, 1, 1536, nullptr,
             nullptr, 0, 0, Wa, BH, 1024, 1024, 1024, 1, nullptr);           // Whh^2 -> Wa
    launch_g(Wa, BH, 1024, 1024, Wa, 1, 1024, nullptr,
             nullptr, 0, 0, Wb, BH, 1024, 1024, 1024, 1, nullptr);           // ^4 -> Wb
    launch_g(Wb, BH, 1024, 1024, Wb, 1, 1024, nullptr,
             nullptr, 0, 0, Wa, BH, 1024, 1024, 1024, 1, nullptr);           // ^8 -> Wa
    launch_g(Wa, BH, 1024, 1024, Wa, 1, 1024, nullptr,
             nullptr, 0, 0, Wb, BH, 1024, 1024, 1024, 1, nullptr);           // ^16 -> Wb

    // 3) p_{j,1} = u_{16j}
    k_initP<<<2048, 1024>>>(P0, U);

    // 4) block-local prefix finals: p_{j,i+1} = p_{j,i} @ Whh^T + u_{16j+i}, i = 1..15
    float* Pc = P0; float* Pn = P1;
    for (int i = 1; i <= 15; i++) {
        launch_g(Pc, BH, 1024, 2048, Whh, 1536, 1, nullptr,
                 U + (long long)i * BH, 16 * BH, 1024,
                 Pn, BH, 1024, 1024, 1024, 1, nullptr);
        float* t = Pc; Pc = Pn; Pn = t;
    }   // final p_{j,16} in Pc

    // 5) boundary scan: h_16 = p_0; h_{16(j+1)} = h_{16j} @ W16^T(+) + p_j  (split-K 16)
    cudaMemcpyAsync(Hall + 16 * BH, Pc, BH * sizeof(float), cudaMemcpyDeviceToDevice);
    for (int j = 1; j <= 31; j++) {
        launch_g(Hall + 16LL * j * BH, 0, 1024, 64, Wb, 1024, 1, nullptr,
                 nullptr, 0, 0, nullptr, 0, 0, 1024, 1024, 16, part);
        k_reduce<<<64, 1024>>>(Hall + 16LL * (j + 1) * BH, Pc + 64LL * j * 1024, part);
    }

    // 6) h_0 = 0
    k_zero<<<64, 1024>>>(Hall);

    // 7) refill interiors: H[16j+i+1] = H[16j+i] @ Whh^T + u_{16j+i}, i = 0..14
    //    (i = 15 rows are exactly the boundary values already in place)
    for (int i = 0; i < 15; i++) {
        launch_g(Hall + (long long)i * BH, 16 * BH, 1024, 2048, Whh, 1536, 1, nullptr,
                 U + (long long)i * BH, 16 * BH, 1024,
                 Hall + (long long)(i + 1) * BH, 16 * BH, 1024, 1024, 1024, 1, nullptr);
    }

    // 8) out_t = x_t @ Wxo^T + b_i2o + h_t @ Who^T   (two accumulating GEMMs)
    launch_g(x, 64 * 512, 512, SEQ * BAT, Wi2o, 1536, 1, bi2o,
             nullptr, 0, 0, OUTb, 64 * 512, 512, 512, 512, 1, nullptr);
    launch_g(Hall, BH, 1024, SEQ * BAT, Wi2o + 512, 1536, 1, nullptr,
             OUTb, 64 * 512, 512, OUTb, 64 * 512, 512, 1024, 512, 1, nullptr);

    // 9) oc_t = out_t @ W1^T + b_o2o + h_{t+1} @ W2^T  -> d_out
    launch_g(OUTb, 64 * 512, 512, SEQ * BAT, Wo2o, 1536, 1, bo2o,
             nullptr, 0, 0, out, 64 * 512, 512, 512, 512, 1, nullptr);
    launch_g(Hall + BH, BH, 1024, SEQ * BAT, Wo2o + 512, 1536, 1, nullptr,
             out, 64 * 512, 512, out, 64 * 512, 512, 1024, 512, 1, nullptr);

    // 10) masked log-softmax, in place on d_out
    k_logsm<<<SEQ * BAT / 8, 256>>>(out, mask);
}

// round 7
// speedup vs baseline: 1.0017x; 1.0017x over previous
#include <cuda_runtime.h>
#include <cstdint>

// Problem dims
#define SEQ  512
#define BAT  64
#define INP  512
#define HID  1024
#define OUTD 512
#define BH   (64LL * 1024)   // elements per timestep slice of U / Hall (BAT*HID)

// ---------------- static device scratch (allocations are forbidden) ----------------
__device__ float g_U   [SEQ * BAT * HID];          // u_t = x_t @ Wxh^T + b_i2h
__device__ float g_Hall[(SEQ + 1) * BAT * HID];    // h_t, t = 0..512
__device__ float g_P0  [2048 * HID];               // block-local prefix (ping)
__device__ float g_P1  [2048 * HID];               // (pong)
__device__ float g_Wa  [HID * HID];                // Whh^2 / Whh^8
__device__ float g_Wb  [HID * HID];                // Whh^4 / Whh^16
__device__ float g_part[16 * BAT * HID];           // split-K partials (boundary)
__device__ float g_OUT [SEQ * BAT * OUTD];         // out_t

// ---------------- GEMM: C[r][n] = sum_k A(r,k) * B(n,k) (+bias)(+Add) ----------------
// Row addressing supports block-scatter: addr(r) = base + (r>>6)*Outer + (r&63)*Inner.
struct GP {
    const float* A; long long aO, aI; int M;       // M = real row count (clamped loads)
    const float* W; long long wn, wk;              // B(n,k) = W[n*wn + k*wk]; wk==1 -> NT
    const float* bias;                             // nullable, indexed by global n
    const float* Add; long long adO, adI;          // nullable, same row mapping as C
    float* C; long long cO, cI;
    int K, N;                                      // K is per-z when gridDim.z > 1
    float* part; long long partStride;             // split-K output: part + z*stride, ld N
};

__device__ __forceinline__ unsigned long long dup2f(float v) {
    unsigned u = __float_as_uint(v);
    unsigned long long d;
    asm("mov.b64 %0, {%1, %1};" : "=l"(d) : "r"(u));
    return d;
}
__device__ __forceinline__ void fma2(unsigned long long& d, unsigned long long a, unsigned long long b) {
    asm("fma.rn.f32x2 %0, %1, %2, %0;" : "+l"(d) : "l"(a), "l"(b));
}

__global__ __launch_bounds__(256, 1) void k_gemm(GP g) {
    __shared__ float As[2][16][128];   // [k][m]
    __shared__ float Bs[2][16][128];   // [k][n]
    const int tid = threadIdx.x;
    const int tx = tid & 15, ty = tid >> 4;          // 16 x 16 threads, 8x8 microtile
    const long long n0 = (long long)blockIdx.x * 128;
    const int mbase = blockIdx.y * 128;
    const int z = blockIdx.z;
    const bool split = (gridDim.z > 1);
    const bool wk1 = (g.wk == 1);

    const float* Abase = g.A + (split ? (long long)z * g.K : 0);   // A is k-contiguous
    const float* Wbase = g.W + (split ? (long long)z * g.K * g.wk : 0);

    // per-thread gmem assignments: 2 float4 for A, 2 float4 for B per k-tile
    const float* ap[2]; int am[2], akq[2];
    const float* bp[2]; int bi0[2], bi1[2];
    #pragma unroll
    for (int q = 0; q < 2; q++) {
        int s = tid * 2 + q;
        am[q] = s >> 2; akq[q] = s & 3;
        int mm = mbase + am[q]; if (mm > g.M - 1) mm = g.M - 1;   // clamp (M=64 case)
        ap[q] = Abase + (long long)(mm >> 6) * g.aO + (long long)(mm & 63) * g.aI + akq[q] * 4;
        if (wk1) {            // NT: k contiguous in W
            bi0[q] = s >> 2;  // n (0..127)
            bi1[q] = s & 3;   // k-quad
            bp[q] = Wbase + (n0 + bi0[q]) * g.wn + bi1[q] * 4;
        } else {              // NN: n contiguous in W
            bi0[q] = s >> 5;  // k (0..15)
            bi1[q] = s & 31;  // n-quad
            bp[q] = Wbase + (long long)bi0[q] * g.wk + n0 + bi1[q] * 4;
        }
    }

    unsigned long long acc[8][4];
    #pragma unroll
    for (int i = 0; i < 8; i++)
        #pragma unroll
        for (int j = 0; j < 4; j++) acc[i][j] = 0ull;

    const int nIter = g.K >> 4;
    float4 va[2], vb[2];

    auto loadT = [&](int k0) {
        #pragma unroll
        for (int q = 0; q < 2; q++) va[q] = *(const float4*)(ap[q] + k0);
        if (wk1) {
            #pragma unroll
            for (int q = 0; q < 2; q++) vb[q] = *(const float4*)(bp[q] + k0);
        } else {
            #pragma unroll
            for (int q = 0; q < 2; q++) vb[q] = *(const float4*)(bp[q] + (long long)k0 * g.wk);
        }
    };
    auto storeT = [&](int buf) {
        #pragma unroll
        for (int q = 0; q < 2; q++) {
            As[buf][akq[q]*4+0][am[q]] = va[q].x;
            As[buf][akq[q]*4+1][am[q]] = va[q].y;
            As[buf][akq[q]*4+2][am[q]] = va[q].z;
            As[buf][akq[q]*4+3][am[q]] = va[q].w;
            if (wk1) {
                Bs[buf][bi1[q]*4+0][bi0[q]] = vb[q].x;
                Bs[buf][bi1[q]*4+1][bi0[q]] = vb[q].y;
                Bs[buf][bi1[q]*4+2][bi0[q]] = vb[q].z;
                Bs[buf][bi1[q]*4+3][bi0[q]] = vb[q].w;
            } else {
                *(float4*)&Bs[buf][bi0[q]][bi1[q]*4] = vb[q];
            }
        }
    };

    loadT(0); storeT(0);
    __syncthreads();

    for (int it = 0; it < nIter; it++) {
        const int cur = it & 1;
        const bool pf = (it + 1 < nIter);
        if (pf) loadT((it + 1) << 4);
        #pragma unroll
        for (int k = 0; k < 16; k++) {
            float4 a0 = *(const float4*)&As[cur][k][ty*8];
            float4 a1 = *(const float4*)&As[cur][k][ty*8 + 4];
            ulonglong2 b0 = *(const ulonglong2*)&Bs[cur][k][tx*8];
            ulonglong2 b1 = *(const ulonglong2*)&Bs[cur][k][tx*8 + 4];
            unsigned long long ad[8];
            ad[0] = dup2f(a0.x); ad[1] = dup2f(a0.y); ad[2] = dup2f(a0.z); ad[3] = dup2f(a0.w);
            ad[4] = dup2f(a1.x); ad[5] = dup2f(a1.y); ad[6] = dup2f(a1.z); ad[7] = dup2f(a1.w);
            unsigned long long bv[4] = {b0.x, b0.y, b1.x, b1.y};
            #pragma unroll
            for (int i = 0; i < 8; i++)
                #pragma unroll
                for (int j = 0; j < 4; j++) fma2(acc[i][j], ad[i], bv[j]);
        }
        if (pf) storeT(cur ^ 1);
        __syncthreads();
    }

    if (split) {
        float* P = g.part + (long long)z * g.partStride;
        #pragma unroll
        for (int i = 0; i < 8; i++) {
            int r = mbase + ty*8 + i;
            if (r < g.M) {
                #pragma unroll
                for (int j = 0; j < 4; j++) {
                    float2 v;
                    v.x = __uint_as_float((unsigned)(acc[i][j]));
                    v.y = __uint_as_float((unsigned)(acc[i][j] >> 32));
                    *(float2*)(P + (long long)r * g.N + n0 + tx*8 + j*2) = v;
                }
            }
        }
    } else {
        #pragma unroll
        for (int i = 0; i < 8; i++) {
            int r = mbase + ty*8 + i;
            if (r < g.M) {
                long long ro = (long long)(r >> 6) * g.cO + (long long)(r & 63) * g.cI;
                #pragma unroll
                for (int j = 0; j < 4; j++) {
                    long long n = n0 + tx*8 + j*2;
                    float2 v;
                    v.x = __uint_as_float((unsigned)(acc[i][j]));
                    v.y = __uint_as_float((unsigned)(acc[i][j] >> 32));
                    if (g.bias) { v.x += g.bias[n]; v.y += g.bias[n + 1]; }
                    if (g.Add) {
                        const float* adp = g.Add + (long long)(r >> 6) * g.adO
                                         + (long long)(r & 63) * g.adI + n;
                        v.x += adp[0]; v.y += adp[1];
                    }
                    *(float2*)(g.C + ro + n) = v;
                }
            }
        }
    }
}

// ---------------- small helpers ----------------
// P0[g][n] = U[16*(g/64)][g%64][n]  (p_{j,1} = u_{16j})
__global__ void k_initP(float* P, const float* U) {
    long long gI = blockIdx.x; int n = threadIdx.x;
    P[gI * 1024 + n] = U[(gI >> 6) * (16 * BH) + (gI & 63) * 1024 + n];
}
__global__ void k_zero(float* p) { p[(long long)blockIdx.x * 1024 + threadIdx.x] = 0.f; }

// dst[i] = p[i] + sum_z part[z][i], i < 65536, Z = 16
__global__ void k_reduce(float* dst, const float* p, const float* part) {
    long long i = (long long)blockIdx.x * 1024 + threadIdx.x;
    float s = p[i];
    #pragma unroll
    for (int z = 0; z < 16; z++) s += part[(long long)z * BH + i];
    dst[i] = s;
}

// y = logits * mask; y -= logsumexp(y). One warp per 512-wide row.
__global__ void k_logsm(float* io, const float* mask) {
    int row  = blockIdx.x * 8 + (threadIdx.x >> 5);
    int lane = threadIdx.x & 31;
    long long base = (long long)row * OUTD + lane;
    float v[16]; float mx = -1e30f;
    #pragma unroll
    for (int i = 0; i < 16; i++) {
        v[i] = io[base + 32 * i] * mask[base + 32 * i];
        mx = fmaxf(mx, v[i]);
    }
    #pragma unroll
    for (int o = 16; o > 0; o >>= 1) mx = fmaxf(mx, __shfl_xor_sync(0xffffffffu, mx, o));
    float s = 0.f;
    #pragma unroll
    for (int i = 0; i < 16; i++) s += expf(v[i] - mx);
    #pragma unroll
    for (int o = 16; o > 0; o >>= 1) s += __shfl_xor_sync(0xffffffffu, s, o);
    float lse = mx + logf(s);
    #pragma unroll
    for (int i = 0; i < 16; i++) io[base + 32 * i] = v[i] - lse;
}

// ---------------- host orchestration ----------------
static inline void launch_g(const float* A, long long aO, long long aI, int M,
                            const float* W, long long wn, long long wk,
                            const float* bias,
                            const float* Add, long long adO, long long adI,
                            float* C, long long cO, long long cI,
                            int K, int N, int Z, float* part)
{
    GP g;
    g.A = A; g.aO = aO; g.aI = aI; g.M = M;
    g.W = W; g.wn = wn; g.wk = wk;
    g.bias = bias; g.Add = Add; g.adO = adO; g.adI = adI;
    g.C = C; g.cO = cO; g.cI = cI;
    g.K = (Z > 1) ? (K / Z) : K; g.N = N;
    g.part = part; g.partStride = BH;
    dim3 grid(N / 128, (M + 127) / 128, Z);
    k_gemm<<<grid, 256>>>(g);
}

extern "C" void kernel_launch(void* const* d_in, const int* in_sizes, int n_in,
                              void* d_out, int out_size)
{
    const float* x    = (const float*)d_in[0];   // [512,64,512]
    const float* mask = (const float*)d_in[1];   // [512,64,512]
    const float* Wi2h = (const float*)d_in[2];   // [1024,1536]
    const float* bi2h = (const float*)d_in[3];   // [1024]
    const float* Wi2o = (const float*)d_in[4];   // [512,1536]
    const float* bi2o = (const float*)d_in[5];   // [512]
    const float* Wo2o = (const float*)d_in[6];   // [512,1536]
    const float* bo2o = (const float*)d_in[7];   // [512]
    float* out = (float*)d_out;                  // [512,64,512] log-probs
    (void)in_sizes; (void)n_in; (void)out_size;

    float *U, *Hall, *P0, *P1, *Wa, *Wb, *part, *OUTb;
    cudaGetSymbolAddress((void**)&U,    g_U);
    cudaGetSymbolAddress((void**)&Hall, g_Hall);
    cudaGetSymbolAddress((void**)&P0,   g_P0);
    cudaGetSymbolAddress((void**)&P1,   g_P1);
    cudaGetSymbolAddress((void**)&Wa,   g_Wa);
    cudaGetSymbolAddress((void**)&Wb,   g_Wb);
    cudaGetSymbolAddress((void**)&part, g_part);
    cudaGetSymbolAddress((void**)&OUTb, g_OUT);

    const float* Whh = Wi2h + 512;   // [1024,1024] slice, row stride 1536

    // 1) U = X @ Wxh^T + b_i2h   (M=32768, N=1024, K=512)
    launch_g(x, 64 * 512, 512, SEQ * BAT, Wi2h, 1536, 1, bi2h,
             nullptr, 0, 0, U, BH, 1024, 512, 1024, 1, nullptr);

    // 2) W16 = Whh^16 via 4 squarings (C = A @ B, B in NN layout: wn=1)
    launch_g(Whh, 64 * 1536, 1536, 1024, Whh, 1, 1536, nullptr,
             nullptr, 0, 0, Wa, BH, 1024, 1024, 1024, 1, nullptr);           // Whh^2 -> Wa
    launch_g(Wa, BH, 1024, 1024, Wa, 1, 1024, nullptr,
             nullptr, 0, 0, Wb, BH, 1024, 1024, 1024, 1, nullptr);           // ^4 -> Wb
    launch_g(Wb, BH, 1024, 1024, Wb, 1, 1024, nullptr,
             nullptr, 0, 0, Wa, BH, 1024, 1024, 1024, 1, nullptr);           // ^8 -> Wa
    launch_g(Wa, BH, 1024, 1024, Wa, 1, 1024, nullptr,
             nullptr, 0, 0, Wb, BH, 1024, 1024, 1024, 1, nullptr);           // ^16 -> Wb

    // 3) p_{j,1} = u_{16j}
    k_initP<<<2048, 1024>>>(P0, U);

    // 4) block-local prefix finals: p_{j,i+1} = p_{j,i} @ Whh^T + u_{16j+i}, i = 1..15
    float* Pc = P0; float* Pn = P1;
    for (int i = 1; i <= 15; i++) {
        launch_g(Pc, BH, 1024, 2048, Whh, 1536, 1, nullptr,
                 U + (long long)i * BH, 16 * BH, 1024,
                 Pn, BH, 1024, 1024, 1024, 1, nullptr);
        float* t = Pc; Pc = Pn; Pn = t;
    }   // final p_{j,16} in Pc

    // 5) boundary scan: h_16 = p_0; h_{16(j+1)} = h_{16j} @ W16^T(+) + p_j  (split-K 16)
    cudaMemcpyAsync(Hall + 16 * BH, Pc, BH * sizeof(float), cudaMemcpyDeviceToDevice);
    for (int j = 1; j <= 31; j++) {
        launch_g(Hall + 16LL * j * BH, 0, 1024, 64, Wb, 1024, 1, nullptr,
                 nullptr, 0, 0, nullptr, 0, 0, 1024, 1024, 16, part);
        k_reduce<<<64, 1024>>>(Hall + 16LL * (j + 1) * BH, Pc + 64LL * j * 1024, part);
    }

    // 6) h_0 = 0
    k_zero<<<64, 1024>>>(Hall);

    // 7) refill interiors: H[16j+i+1] = H[16j+i] @ Whh^T + u_{16j+i}, i = 0..14
    //    (i = 15 rows are exactly the boundary values already in place)
    for (int i = 0; i < 15; i++) {
        launch_g(Hall + (long long)i * BH, 16 * BH, 1024, 2048, Whh, 1536, 1, nullptr,
                 U + (long long)i * BH, 16 * BH, 1024,
                 Hall + (long long)(i + 1) * BH, 16 * BH, 1024, 1024, 1024, 1, nullptr);
    }

    // 8) out_t = x_t @ Wxo^T + b_i2o + h_t @ Who^T   (two accumulating GEMMs)
    launch_g(x, 64 * 512, 512, SEQ * BAT, Wi2o, 1536, 1, bi2o,
             nullptr, 0, 0, OUTb, 64 * 512, 512, 512, 512, 1, nullptr);
    launch_g(Hall, BH, 1024, SEQ * BAT, Wi2o + 512, 1536, 1, nullptr,
             OUTb, 64 * 512, 512, OUTb, 64 * 512, 512, 1024, 512, 1, nullptr);

    // 9) oc_t = out_t @ W1^T + b_o2o + h_{t+1} @ W2^T  -> d_out
    launch_g(OUTb, 64 * 512, 512, SEQ * BAT, Wo2o, 1536, 1, bo2o,
             nullptr, 0, 0, out, 64 * 512, 512, 512, 512, 1, nullptr);
    launch_g(Hall + BH, BH, 1024, SEQ * BAT, Wo2o + 512, 1536, 1, nullptr,
             out, 64 * 512, 512, out, 64 * 512, 512, 1024, 512, 1, nullptr);

    // 10) masked log-softmax, in place on d_out
    k_logsm<<<SEQ * BAT / 8, 256>>>(out, mask);
}

// round 9
// speedup vs baseline: 1.7703x; 1.7673x over previous
#include <cuda_runtime.h>
#include <cuda_fp16.h>
#include <cstdint>

#define SEQ 512
#define BAT 64
#define HID 1024
#define OUTD 512
#define BH 65536LL   // BAT*HID

struct Scratch {
    float  U [SEQ*BAT*HID];
    __half Uh[SEQ*BAT*HID], Ul[SEQ*BAT*HID];
    float  Hall[SEQ*BAT*HID];                       // f32 shadow (write-only)
    __half Hh[(SEQ+1)*BAT*HID], Hl[(SEQ+1)*BAT*HID];
    float  P [2][2048*HID];
    __half Ph[2][2048*HID], Pl[2][2048*HID];
    float  S [2][33*BAT*HID];
    __half Sh[2][33*BAT*HID], Sl[2][33*BAT*HID];
    float  OUT[SEQ*BAT*OUTD];
    __half Oh[SEQ*BAT*OUTD], Ol[SEQ*BAT*OUTD];
    __half xh[SEQ*BAT*512], xl[SEQ*BAT*512];
    __half W1h[HID*1536],  W1l[HID*1536];
    __half W2h[OUTD*1536], W2l[OUTD*1536];
    __half W3h[OUTD*1536], W3l[OUTD*1536];
    float  Wf[2][HID*HID];
    __half Th[HID*HID], Tl[HID*HID];
    __half PWh[8][HID*HID], PWl[8][HID*HID];        // W^(2^(k+1)) hi/lo
};
__device__ Scratch g;

// ---------------- PTX helpers (baseline PTX only: sm_80+) ----------------
__device__ __forceinline__ uint32_t s2u(const void* p) {
    uint32_t a;
    asm("{ .reg .u64 t; cvta.to.shared.u64 t, %1; cvt.u32.u64 %0, t; }" : "=r"(a) : "l"(p));
    return a;
}
#define CP16(d,s) asm volatile("cp.async.cg.shared.global [%0], [%1], 16;" :: "r"(d), "l"(s) : "memory")
#define CPC() asm volatile("cp.async.commit_group;" ::: "memory")
#define CPW(n) asm volatile("cp.async.wait_group %0;" :: "n"(n) : "memory")
#define LDM4(r0,r1,r2,r3,a) \
    asm volatile("ldmatrix.sync.aligned.m8n8.x4.shared.b16 {%0,%1,%2,%3}, [%4];" \
        : "=r"(r0), "=r"(r1), "=r"(r2), "=r"(r3) : "r"(a))
#define MMA(d,a,b0,b1) \
    asm volatile("mma.sync.aligned.m16n8k16.row.col.f32.f16.f16.f32 " \
        "{%0,%1,%2,%3},{%4,%5,%6,%7},{%8,%9},{%0,%1,%2,%3};" \
        : "+f"((d)[0]), "+f"((d)[1]), "+f"((d)[2]), "+f"((d)[3]) \
        : "r"((a)[0]), "r"((a)[1]), "r"((a)[2]), "r"((a)[3]), "r"(b0), "r"(b1))

// ---------------- warp-MMA multi-segment GEMM ----------------
// C[r][n] = sum_seg sum_k A_s(r,k)*B_s(n,k) (+bias[n]) (+Add(r,n))
// row addr: (r>>6)*aO + (r&63)*aI ; B rows n are k-contiguous (stride wn).
struct TSeg { const __half *A, *B; long long aO, aI, wn; int kt; };
struct TGP {
    TSeg s[6]; int ns, M;
    const float *bias, *Add; long long adO, adI;
    float* C; __half *Chi, *Clo; long long cO, cI;
};
#define TG_SMEM 65536

__global__ __launch_bounds__(256) void k_tgemm(TGP p) {
    extern __shared__ char sm[];
    const uint32_t sb = s2u(sm);
    const int tid = threadIdx.x, lane = tid & 31, wid = tid >> 5;
    const int wm = wid & 3, wn = wid >> 2;          // 4 x 2 warp grid (32 x 64 tiles)
    const int mb = blockIdx.y * 128;
    const long long n0 = (long long)blockIdx.x * 128;
    const uint32_t BUF[2] = { sb, sb + 32768 };     // [A 16K | B 16K] per buffer

    // gmem->smem: each thread owns half a row (4 x 16B chunks) of A and of B
    const int rowp = tid >> 1;
    uint32_t lo[4];
    #pragma unroll
    for (int c = 0; c < 4; c++) {
        uint32_t o = rowp*128 + ((tid&1)*4 + c)*16;
        lo[c] = o ^ ((o >> 3) & 0x70);
    }
    int ma = mb + rowp; if (ma > p.M - 1) ma = p.M - 1;
    const long long nrow = n0 + rowp;

    int T = 0;
    for (int s = 0; s < p.ns; s++) T += p.s[s].kt;
    int ls = 0, lk = 0;
    auto load = [&](int buf) {
        const TSeg& sg = p.s[ls];
        const __half* a = sg.A + (long long)(ma>>6)*sg.aO + (long long)(ma&63)*sg.aI
                        + (long long)lk*64 + (tid&1)*32;
        const __half* b = sg.B + nrow*sg.wn + (long long)lk*64 + (tid&1)*32;
        #pragma unroll
        for (int c = 0; c < 4; c++) {
            CP16(BUF[buf] + lo[c], a + c*8);
            CP16(BUF[buf] + 16384 + lo[c], b + c*8);
        }
        CPC();
        if (++lk == sg.kt) { lk = 0; ls++; }
    };

    float acc[2][8][4];
    #pragma unroll
    for (int i = 0; i < 2; i++)
        #pragma unroll
        for (int j = 0; j < 8; j++)
            #pragma unroll
            for (int q = 0; q < 4; q++) acc[i][j][q] = 0.f;

    // ldmatrix row bases (x4: lanes 0-15 -> rows 0-15 klo, lanes 16-31 -> rows khi)
    uint32_t arow[2], brow[4];
    #pragma unroll
    for (int mi = 0; mi < 2; mi++) arow[mi] = (uint32_t)(wm*32 + mi*16 + (lane & 15)) * 128;
    #pragma unroll
    for (int ni = 0; ni < 4; ni++) brow[ni] = (uint32_t)(wn*64 + ni*16 + (lane & 15)) * 128;
    const uint32_t kcol = (uint32_t)(lane >> 4) * 16;

    load(0);
    for (int t = 0; t < T; t++) {
        const int buf = t & 1;
        if (t + 1 < T) { load(buf ^ 1); CPW(1); } else CPW(0);
        __syncthreads();
        #pragma unroll
        for (int ks = 0; ks < 4; ks++) {
            uint32_t af[2][4], bf[4][4];
            #pragma unroll
            for (int mi = 0; mi < 2; mi++) {
                uint32_t o = arow[mi] + ks*32 + kcol;
                o ^= (o >> 3) & 0x70;
                LDM4(af[mi][0], af[mi][1], af[mi][2], af[mi][3], BUF[buf] + o);
            }
            #pragma unroll
            for (int ni = 0; ni < 4; ni++) {
                uint32_t o = brow[ni] + ks*32 + kcol;
                o ^= (o >> 3) & 0x70;
                LDM4(bf[ni][0], bf[ni][1], bf[ni][2], bf[ni][3], BUF[buf] + 16384 + o);
            }
            // B x4 matrix order: M0=n0-7/klo, M1=n8-15/klo, M2=n0-7/khi, M3=n8-15/khi
            // -> n8-block0 frag = {r0, r2}, block1 = {r1, r3}
            #pragma unroll
            for (int mi = 0; mi < 2; mi++)
                #pragma unroll
                for (int gq = 0; gq < 4; gq++) {
                    MMA(acc[mi][2*gq],     af[mi], bf[gq][0], bf[gq][2]);
                    MMA(acc[mi][2*gq + 1], af[mi], bf[gq][1], bf[gq][3]);
                }
        }
        __syncthreads();
    }

    // epilogue: c-frag regs {0,1}=row lane/4, {2,3}=row lane/4+8; cols (lane&3)*2
    #pragma unroll
    for (int mi = 0; mi < 2; mi++)
        #pragma unroll
        for (int hh = 0; hh < 2; hh++) {
            const int row = mb + wm*32 + mi*16 + (lane >> 2) + hh*8;
            if (row < p.M) {
                const long long rb = (long long)(row>>6)*p.cO + (long long)(row&63)*p.cI;
                const long long ab = p.Add ? (long long)(row>>6)*p.adO + (long long)(row&63)*p.adI : 0;
                #pragma unroll
                for (int nb = 0; nb < 8; nb++) {
                    const long long col = n0 + wn*64 + nb*8 + (lane & 3)*2;
                    float v0 = acc[mi][nb][hh*2], v1 = acc[mi][nb][hh*2 + 1];
                    if (p.bias) { v0 += p.bias[col]; v1 += p.bias[col + 1]; }
                    if (p.Add) { float2 ad = *(const float2*)(p.Add + ab + col); v0 += ad.x; v1 += ad.y; }
                    *(float2*)(p.C + rb + col) = make_float2(v0, v1);
                    if (p.Chi) {
                        __half h0 = __float2half_rn(v0), h1 = __float2half_rn(v1);
                        *(__half2*)(p.Chi + rb + col) = __halves2half2(h0, h1);
                        *(__half2*)(p.Clo + rb + col) = __halves2half2(
                            __float2half_rn(v0 - __half2float(h0)),
                            __float2half_rn(v1 - __half2float(h1)));
                    }
                }
            }
        }
}

// ---------------- small kernels ----------------
__global__ void k_cvt(__half* h, __half* l, const float* s, int n) {
    int i = blockIdx.x*1024 + threadIdx.x;
    if (i < n) {
        float v = s[i];
        __half a = __float2half_rn(v);
        h[i] = a; l[i] = __float2half_rn(v - __half2float(a));
    }
}
__global__ void k_transp(__half* th, __half* tl, const float* src, int stride) {
    int i = blockIdx.x, j = threadIdx.x;                 // out[i][j] = src[j][i]
    float v = src[(long long)j*stride + i];
    __half a = __float2half_rn(v);
    th[i*1024 + j] = a; tl[i*1024 + j] = __float2half_rn(v - __half2float(a));
}
__global__ void k_zero3(float* f, __half* h, __half* l) {
    int i = blockIdx.x*1024 + threadIdx.x;
    f[i] = 0.f; h[i] = __float2half_rn(0.f); l[i] = __float2half_rn(0.f);
}
__global__ void k_scatter(__half* Hh, __half* Hl, const __half* Sh, const __half* Sl) {
    long long i = (long long)blockIdx.x*1024 + threadIdx.x;   // < 33*BH
    long long j = i >> 16, e = i & 65535;
    Hh[j*16*BH + e] = Sh[i];
    Hl[j*16*BH + e] = Sl[i];
}
__global__ void k_logsm(float* io, const float* mask) {
    int row = blockIdx.x*8 + (threadIdx.x >> 5), lane = threadIdx.x & 31;
    long long b = (long long)row*OUTD + lane;
    float v[16], mx = -1e30f;
    #pragma unroll
    for (int i = 0; i < 16; i++) { v[i] = io[b+32*i] * mask[b+32*i]; mx = fmaxf(mx, v[i]); }
    #pragma unroll
    for (int o = 16; o; o >>= 1) mx = fmaxf(mx, __shfl_xor_sync(~0u, mx, o));
    float s = 0.f;
    #pragma unroll
    for (int i = 0; i < 16; i++) s += expf(v[i] - mx);
    #pragma unroll
    for (int o = 16; o; o >>= 1) s += __shfl_xor_sync(~0u, s, o);
    float lse = mx + logf(s);
    #pragma unroll
    for (int i = 0; i < 16; i++) io[b+32*i] = v[i] - lse;
}

// ---------------- host ----------------
static TSeg mkseg(const __half* A, long long aO, long long aI,
                  const __half* B, long long wn, int kt) {
    TSeg t; t.A = A; t.aO = aO; t.aI = aI; t.B = B; t.wn = wn; t.kt = kt; return t;
}
static void tg(const TSeg* s, int ns, int M, int N, const float* bias,
               const float* Add, long long adO, long long adI,
               float* C, __half* Chi, __half* Clo, long long cO, long long cI) {
    TGP p;
    for (int i = 0; i < ns; i++) p.s[i] = s[i];
    p.ns = ns; p.M = M; p.bias = bias; p.Add = Add; p.adO = adO; p.adI = adI;
    p.C = C; p.Chi = Chi; p.Clo = Clo; p.cO = cO; p.cI = cI;
    k_tgemm<<<dim3(N/128, (M+127)/128), 256, TG_SMEM>>>(p);
}

extern "C" void kernel_launch(void* const* d_in, const int* in_sizes, int n_in,
                              void* d_out, int out_size)
{
    const float* x    = (const float*)d_in[0];
    const float* mask = (const float*)d_in[1];
    const float* Wi2h = (const float*)d_in[2];
    const float* bi2h = (const float*)d_in[3];
    const float* Wi2o = (const float*)d_in[4];
    const float* bi2o = (const float*)d_in[5];
    const float* Wo2o = (const float*)d_in[6];
    const float* bo2o = (const float*)d_in[7];
    float* out = (float*)d_out;
    (void)in_sizes; (void)n_in; (void)out_size;

    cudaFuncSetAttribute(k_tgemm, cudaFuncAttributeMaxDynamicSharedMemorySize, TG_SMEM);
    Scratch* s; cudaGetSymbolAddress((void**)&s, g);
    const float* Whh = Wi2h + 512;

    // converts
    k_cvt<<<16384,1024>>>(s->xh, s->xl, x, SEQ*BAT*512);
    k_cvt<<<1536,1024>>>(s->W1h, s->W1l, Wi2h, HID*1536);
    k_cvt<<<768,1024>>>(s->W2h, s->W2l, Wi2o, OUTD*1536);
    k_cvt<<<768,1024>>>(s->W3h, s->W3l, Wo2o, OUTD*1536);

    // U = x @ Wxh^T + b
    {
        TSeg sg[3] = { mkseg(s->xh, 32768, 512, s->W1h, 1536, 8),
                       mkseg(s->xl, 32768, 512, s->W1h, 1536, 8),
                       mkseg(s->xh, 32768, 512, s->W1l, 1536, 8) };
        tg(sg, 3, SEQ*BAT, HID, bi2h, nullptr, 0, 0, s->U, s->Uh, s->Ul, BH, 1024);
    }
    // powers W^2 .. W^256 (squarings: W^2p = W^p @ (W^p ^T)^T, B = transpose)
    for (int k = 0; k < 8; k++) {
        k_transp<<<1024,1024>>>(s->Th, s->Tl, k ? s->Wf[(k-1)&1] : Whh, k ? 1024 : 1536);
        const __half* Ah = k ? s->PWh[k-1] : s->W1h + 512;
        const __half* Al = k ? s->PWl[k-1] : s->W1l + 512;
        long long aI = k ? 1024 : 1536;
        TSeg sg[3] = { mkseg(Ah, 64*aI, aI, s->Th, 1024, 16),
                       mkseg(Al, 64*aI, aI, s->Th, 1024, 16),
                       mkseg(Ah, 64*aI, aI, s->Tl, 1024, 16) };
        tg(sg, 3, HID, HID, nullptr, nullptr, 0, 0, s->Wf[k&1], s->PWh[k], s->PWl[k], BH, 1024);
    }
    // block prefixes: p_{j,i+1} = p_{j,i} @ Whh^T + u_{16j+i}
    int cur = 0;
    for (int i = 1; i <= 15; i++) {
        const __half* Ah = (i == 1) ? s->Uh : s->Ph[cur];
        const __half* Al = (i == 1) ? s->Ul : s->Pl[cur];
        long long aO = (i == 1) ? 16*BH : BH;
        TSeg sg[3] = { mkseg(Ah, aO, 1024, s->W1h + 512, 1536, 16),
                       mkseg(Al, aO, 1024, s->W1h + 512, 1536, 16),
                       mkseg(Ah, aO, 1024, s->W1l + 512, 1536, 16) };
        if (i < 15) {
            tg(sg, 3, 2048, HID, nullptr, s->U + (long long)i*BH, 16*BH, 1024,
               s->P[cur^1], s->Ph[cur^1], s->Pl[cur^1], BH, 1024);
            cur ^= 1;
        } else
            tg(sg, 3, 2048, HID, nullptr, s->U + (long long)i*BH, 16*BH, 1024,
               s->S[0] + BH, s->Sh[0] + BH, s->Sl[0] + BH, BH, 1024);
    }
    // Hillis-Steele boundary scan: S[m] += S[m-g] @ (W^16g)^T
    k_zero3<<<64,1024>>>(s->S[0], s->Sh[0], s->Sl[0]);
    int a = 0;
    for (int d = 0; d < 5; d++) {
        const long long gp = 1LL << d;
        cudaMemcpyAsync(s->S[a^1],  s->S[a],  gp*BH*4, cudaMemcpyDeviceToDevice);
        cudaMemcpyAsync(s->Sh[a^1], s->Sh[a], gp*BH*2, cudaMemcpyDeviceToDevice);
        cudaMemcpyAsync(s->Sl[a^1], s->Sl[a], gp*BH*2, cudaMemcpyDeviceToDevice);
        TSeg sg[3] = { mkseg(s->Sh[a], BH, 1024, s->PWh[3+d], 1024, 16),
                       mkseg(s->Sl[a], BH, 1024, s->PWh[3+d], 1024, 16),
                       mkseg(s->Sh[a], BH, 1024, s->PWl[3+d], 1024, 16) };
        tg(sg, 3, (int)((33 - gp)*64), HID, nullptr, s->S[a] + gp*BH, BH, 1024,
           s->S[a^1] + gp*BH, s->Sh[a^1] + gp*BH, s->Sl[a^1] + gp*BH, BH, 1024);
        a ^= 1;
    }
    k_scatter<<<2112,1024>>>(s->Hh, s->Hl, s->Sh[a], s->Sl[a]);
    // refill: H[16j+i+1] = H[16j+i] @ Whh^T + u_{16j+i}
    for (int i = 0; i < 15; i++) {
        const __half* Ah = (i == 0) ? s->Sh[a] : s->Hh + (long long)i*BH;
        const __half* Al = (i == 0) ? s->Sl[a] : s->Hl + (long long)i*BH;
        long long aO = (i == 0) ? BH : 16*BH;
        TSeg sg[3] = { mkseg(Ah, aO, 1024, s->W1h + 512, 1536, 16),
                       mkseg(Al, aO, 1024, s->W1h + 512, 1536, 16),
                       mkseg(Ah, aO, 1024, s->W1l + 512, 1536, 16) };
        tg(sg, 3, 2048, HID, nullptr, s->U + (long long)i*BH, 16*BH, 1024,
           s->Hall + (long long)i*BH, s->Hh + (long long)(i+1)*BH, s->Hl + (long long)(i+1)*BH,
           16*BH, 1024);
    }
    // out = [x, h] @ Wi2o^T + b
    {
        TSeg sg[6] = { mkseg(s->xh, 32768, 512, s->W2h, 1536, 8),
                       mkseg(s->xl, 32768, 512, s->W2h, 1536, 8),
                       mkseg(s->xh, 32768, 512, s->W2l, 1536, 8),
                       mkseg(s->Hh, BH, 1024, s->W2h + 512, 1536, 16),
                       mkseg(s->Hl, BH, 1024, s->W2h + 512, 1536, 16),
                       mkseg(s->Hh, BH, 1024, s->W2l + 512, 1536, 16) };
        tg(sg, 6, SEQ*BAT, OUTD, bi2o, nullptr, 0, 0, s->OUT, s->Oh, s->Ol, 32768, 512);
    }
    // oc = [out, h_next] @ Wo2o^T + b
    {
        TSeg sg[6] = { mkseg(s->Oh, 32768, 512, s->W3h, 1536, 8),
                       mkseg(s->Ol, 32768, 512, s->W3h, 1536, 8),
                       mkseg(s->Oh, 32768, 512, s->W3l, 1536, 8),
                       mkseg(s->Hh + BH, BH, 1024, s->W3h + 512, 1536, 16),
                       mkseg(s->Hl + BH, BH, 1024, s->W3h + 512, 1536, 16),
                       mkseg(s->Hh + BH, BH, 1024, s->W3l + 512, 1536, 16) };
        tg(sg, 6, SEQ*BAT, OUTD, bo2o, nullptr, 0, 0, out, nullptr, nullptr, 32768, 512);
    }
    k_logsm<<<SEQ*BAT/8, 256>>>(out, mask);
}

// round 10
// speedup vs baseline: 1.8809x; 1.0625x over previous
#include <cuda_runtime.h>
#include <cuda_fp16.h>
#include <cstdint>

#define SEQ 512
#define BAT 64
#define HID 1024
#define OUTD 512
#define BH 65536LL   // BAT*HID

struct Scratch {
    float  U [SEQ*BAT*HID];
    __half Uh[SEQ*BAT*HID], Ul[SEQ*BAT*HID];
    __half Hh[(SEQ+1)*BAT*HID], Hl[(SEQ+1)*BAT*HID];
    __half Ph[2][4096*HID], Pl[2][4096*HID];
    float  S [2][65*BAT*HID];
    __half Sh[2][65*BAT*HID], Sl[2][65*BAT*HID];
    __half Oh[SEQ*BAT*OUTD], Ol[SEQ*BAT*OUTD];
    __half xh[SEQ*BAT*512], xl[SEQ*BAT*512];
    __half W1h[HID*1536],  W1l[HID*1536];
    __half W2h[OUTD*1536], W2l[OUTD*1536];
    __half W3h[OUTD*1536], W3l[OUTD*1536];
    float  Wf[2][HID*HID];
    __half Th[HID*HID], Tl[HID*HID];
    __half PWh[8][HID*HID], PWl[8][HID*HID];   // W^(2^(k+1)) hi/lo, k=0..7
};
__device__ Scratch g;

// ---------------- PTX helpers (baseline PTX, sm_80+) ----------------
__device__ __forceinline__ uint32_t s2u(const void* p) {
    uint32_t a;
    asm("{ .reg .u64 t; cvta.to.shared.u64 t, %1; cvt.u32.u64 %0, t; }" : "=r"(a) : "l"(p));
    return a;
}
#define CP16(d,s) asm volatile("cp.async.cg.shared.global [%0], [%1], 16;" :: "r"(d), "l"(s) : "memory")
#define CPC() asm volatile("cp.async.commit_group;" ::: "memory")
#define CPW(n) asm volatile("cp.async.wait_group %0;" :: "n"(n) : "memory")
#define LDM4(r0,r1,r2,r3,a) \
    asm volatile("ldmatrix.sync.aligned.m8n8.x4.shared.b16 {%0,%1,%2,%3}, [%4];" \
        : "=r"(r0), "=r"(r1), "=r"(r2), "=r"(r3) : "r"(a))
#define MMA(d,a,b0,b1) \
    asm volatile("mma.sync.aligned.m16n8k16.row.col.f32.f16.f16.f32 " \
        "{%0,%1,%2,%3},{%4,%5,%6,%7},{%8,%9},{%0,%1,%2,%3};" \
        : "+f"((d)[0]), "+f"((d)[1]), "+f"((d)[2]), "+f"((d)[3]) \
        : "r"((a)[0]), "r"((a)[1]), "r"((a)[2]), "r"((a)[3]), "r"(b0), "r"(b1))

// ---------------- warp-MMA multi-segment GEMM (3-stage pipeline) ----------------
// C[r][n] = sum_seg sum_k A_s(r,k)*B_s(n,k) (+bias[n]) (+Add(r,n))
// row addr: (r>>6)*aO + (r&63)*aI ; B rows n are k-contiguous (stride wn).
struct TSeg { const __half *A, *B; long long aO, aI, wn; int kt; };
struct TGP {
    TSeg s[6]; int ns, M;
    const float *bias, *Add; long long adO, adI;
    float* C; __half *Chi, *Clo; long long cO, cI;   // C / Chi nullable
};
#define TG_SMEM 98304   // 3 stages x (16K A + 16K B)

__global__ __launch_bounds__(256) void k_tgemm(TGP p) {
    extern __shared__ char sm[];
    const uint32_t sb = s2u(sm);
    const int tid = threadIdx.x, lane = tid & 31, wid = tid >> 5;
    const int wm = wid & 3, wn = wid >> 2;          // 4 x 2 warp grid (32 x 64 tiles)
    const int mb = blockIdx.y * 128;
    const long long n0 = (long long)blockIdx.x * 128;
    const uint32_t BUF[3] = { sb, sb + 32768, sb + 65536 };

    // gmem->smem: each thread owns half a row (4 x 16B chunks) of A and of B
    const int rowp = tid >> 1;
    uint32_t lo[4];
    #pragma unroll
    for (int c = 0; c < 4; c++) {
        uint32_t o = rowp*128 + ((tid&1)*4 + c)*16;
        lo[c] = o ^ ((o >> 3) & 0x70);
    }
    int ma = mb + rowp; if (ma > p.M - 1) ma = p.M - 1;
    const long long nrow = n0 + rowp;

    int T = 0;
    for (int s = 0; s < p.ns; s++) T += p.s[s].kt;
    int ls = 0, lk = 0;
    auto load = [&](int buf) {
        const TSeg& sg = p.s[ls];
        const __half* a = sg.A + (long long)(ma>>6)*sg.aO + (long long)(ma&63)*sg.aI
                        + (long long)lk*64 + (tid&1)*32;
        const __half* b = sg.B + nrow*sg.wn + (long long)lk*64 + (tid&1)*32;
        #pragma unroll
        for (int c = 0; c < 4; c++) {
            CP16(BUF[buf] + lo[c], a + c*8);
            CP16(BUF[buf] + 16384 + lo[c], b + c*8);
        }
        CPC();
        if (++lk == sg.kt) { lk = 0; ls++; }
    };

    float acc[2][8][4];
    #pragma unroll
    for (int i = 0; i < 2; i++)
        #pragma unroll
        for (int j = 0; j < 8; j++)
            #pragma unroll
            for (int q = 0; q < 4; q++) acc[i][j][q] = 0.f;

    uint32_t arow[2], brow[4];
    #pragma unroll
    for (int mi = 0; mi < 2; mi++) arow[mi] = (uint32_t)(wm*32 + mi*16 + (lane & 15)) * 128;
    #pragma unroll
    for (int ni = 0; ni < 4; ni++) brow[ni] = (uint32_t)(wn*64 + ni*16 + (lane & 15)) * 128;
    const uint32_t kcol = (uint32_t)(lane >> 4) * 16;

    load(0);
    if (T > 1) load(1);
    for (int t = 0; t < T; t++) {
        if (t + 1 < T) CPW(1); else CPW(0);
        __syncthreads();                           // load t visible; buf (t-1)%3 free
        if (t + 2 < T) load((t + 2) % 3);
        const uint32_t base = BUF[t % 3];
        #pragma unroll
        for (int ks = 0; ks < 4; ks++) {
            uint32_t af[2][4], bf[4][4];
            #pragma unroll
            for (int mi = 0; mi < 2; mi++) {
                uint32_t o = arow[mi] + ks*32 + kcol;
                o ^= (o >> 3) & 0x70;
                LDM4(af[mi][0], af[mi][1], af[mi][2], af[mi][3], base + o);
            }
            #pragma unroll
            for (int ni = 0; ni < 4; ni++) {
                uint32_t o = brow[ni] + ks*32 + kcol;
                o ^= (o >> 3) & 0x70;
                LDM4(bf[ni][0], bf[ni][1], bf[ni][2], bf[ni][3], base + 16384 + o);
            }
            #pragma unroll
            for (int mi = 0; mi < 2; mi++)
                #pragma unroll
                for (int gq = 0; gq < 4; gq++) {
                    MMA(acc[mi][2*gq],     af[mi], bf[gq][0], bf[gq][2]);
                    MMA(acc[mi][2*gq + 1], af[mi], bf[gq][1], bf[gq][3]);
                }
        }
    }

    // epilogue: c-frag regs {0,1}=row lane/4, {2,3}=row lane/4+8; cols (lane&3)*2
    #pragma unroll
    for (int mi = 0; mi < 2; mi++)
        #pragma unroll
        for (int hh = 0; hh < 2; hh++) {
            const int row = mb + wm*32 + mi*16 + (lane >> 2) + hh*8;
            if (row < p.M) {
                const long long rb = (long long)(row>>6)*p.cO + (long long)(row&63)*p.cI;
                const long long ab = p.Add ? (long long)(row>>6)*p.adO + (long long)(row&63)*p.adI : 0;
                #pragma unroll
                for (int nb = 0; nb < 8; nb++) {
                    const long long col = n0 + wn*64 + nb*8 + (lane & 3)*2;
                    float v0 = acc[mi][nb][hh*2], v1 = acc[mi][nb][hh*2 + 1];
                    if (p.bias) { v0 += p.bias[col]; v1 += p.bias[col + 1]; }
                    if (p.Add) { float2 ad = *(const float2*)(p.Add + ab + col); v0 += ad.x; v1 += ad.y; }
                    if (p.C) *(float2*)(p.C + rb + col) = make_float2(v0, v1);
                    if (p.Chi) {
                        __half h0 = __float2half_rn(v0), h1 = __float2half_rn(v1);
                        *(__half2*)(p.Chi + rb + col) = __halves2half2(h0, h1);
                        *(__half2*)(p.Clo + rb + col) = __halves2half2(
                            __float2half_rn(v0 - __half2float(h0)),
                            __float2half_rn(v1 - __half2float(h1)));
                    }
                }
            }
        }
}

// ---------------- small kernels ----------------
__global__ void k_cvt(__half* h, __half* l, const float* s, int n) {
    int i = blockIdx.x*1024 + threadIdx.x;
    if (i < n) {
        float v = s[i];
        __half a = __float2half_rn(v);
        h[i] = a; l[i] = __float2half_rn(v - __half2float(a));
    }
}
// tiled transpose: out[i][j] = src[j][i], out 1024x1024, coalesced both sides
__global__ void k_transp(__half* th, __half* tl, const float* src, int stride) {
    __shared__ float t[32][33];
    int tx = threadIdx.x, ty0 = threadIdx.y;
    int bx = blockIdx.x*32, by = blockIdx.y*32;
    #pragma unroll
    for (int r = 0; r < 4; r++) {
        int ty = ty0*4 + r;
        t[ty][tx] = src[(long long)(by+ty)*stride + bx + tx];
    }
    __syncthreads();
    #pragma unroll
    for (int r = 0; r < 4; r++) {
        int row = ty0*4 + r;
        float v = t[tx][row];
        __half h = __float2half_rn(v);
        long long o = (long long)(bx+row)*1024 + by + tx;
        th[o] = h; tl[o] = __float2half_rn(v - __half2float(h));
    }
}
__global__ void k_zero3(float* f, __half* h, __half* l) {
    int i = blockIdx.x*1024 + threadIdx.x;
    f[i] = 0.f; h[i] = __half(0.f); l[i] = __half(0.f);
}
__global__ void k_scatter(__half* Hh, __half* Hl, const __half* Sh, const __half* Sl) {
    long long i = (long long)blockIdx.x*1024 + threadIdx.x;   // < 65*BH
    long long j = i >> 16, e = i & 65535;
    Hh[j*8*BH + e] = Sh[i];
    Hl[j*8*BH + e] = Sl[i];
}
__global__ void k_logsm(float* io, const float* mask) {
    int row = blockIdx.x*8 + (threadIdx.x >> 5), lane = threadIdx.x & 31;
    long long b = (long long)row*OUTD + lane;
    float v[16], mx = -1e30f;
    #pragma unroll
    for (int i = 0; i < 16; i++) { v[i] = io[b+32*i] * mask[b+32*i]; mx = fmaxf(mx, v[i]); }
    #pragma unroll
    for (int o = 16; o; o >>= 1) mx = fmaxf(mx, __shfl_xor_sync(~0u, mx, o));
    float s = 0.f;
    #pragma unroll
    for (int i = 0; i < 16; i++) s += expf(v[i] - mx);
    #pragma unroll
    for (int o = 16; o; o >>= 1) s += __shfl_xor_sync(~0u, s, o);
    float lse = mx + logf(s);
    #pragma unroll
    for (int i = 0; i < 16; i++) io[b+32*i] = v[i] - lse;
}

// ---------------- host ----------------
static TSeg mkseg(const __half* A, long long aO, long long aI,
                  const __half* B, long long wn, int kt) {
    TSeg t; t.A = A; t.aO = aO; t.aI = aI; t.B = B; t.wn = wn; t.kt = kt; return t;
}
static void tg(const TSeg* s, int ns, int M, int N, const float* bias,
               const float* Add, long long adO, long long adI,
               float* C, __half* Chi, __half* Clo, long long cO, long long cI) {
    TGP p;
    for (int i = 0; i < ns; i++) p.s[i] = s[i];
    p.ns = ns; p.M = M; p.bias = bias; p.Add = Add; p.adO = adO; p.adI = adI;
    p.C = C; p.Chi = Chi; p.Clo = Clo; p.cO = cO; p.cI = cI;
    k_tgemm<<<dim3(N/128, (M+127)/128), 256, TG_SMEM>>>(p);
}

extern "C" void kernel_launch(void* const* d_in, const int* in_sizes, int n_in,
                              void* d_out, int out_size)
{
    const float* x    = (const float*)d_in[0];
    const float* mask = (const float*)d_in[1];
    const float* Wi2h = (const float*)d_in[2];
    const float* bi2h = (const float*)d_in[3];
    const float* Wi2o = (const float*)d_in[4];
    const float* bi2o = (const float*)d_in[5];
    const float* Wo2o = (const float*)d_in[6];
    const float* bo2o = (const float*)d_in[7];
    float* out = (float*)d_out;
    (void)in_sizes; (void)n_in; (void)out_size;

    cudaFuncSetAttribute(k_tgemm, cudaFuncAttributeMaxDynamicSharedMemorySize, TG_SMEM);
    Scratch* s; cudaGetSymbolAddress((void**)&s, g);
    const float* Whh = Wi2h + 512;

    // converts
    k_cvt<<<16384,1024>>>(s->xh, s->xl, x, SEQ*BAT*512);
    k_cvt<<<1536,1024>>>(s->W1h, s->W1l, Wi2h, HID*1536);
    k_cvt<<<768,1024>>>(s->W2h, s->W2l, Wi2o, OUTD*1536);
    k_cvt<<<768,1024>>>(s->W3h, s->W3l, Wo2o, OUTD*1536);

    // U = x @ Wxh^T + b
    {
        TSeg sg[3] = { mkseg(s->xh, 32768, 512, s->W1h, 1536, 8),
                       mkseg(s->xl, 32768, 512, s->W1h, 1536, 8),
                       mkseg(s->xh, 32768, 512, s->W1l, 1536, 8) };
        tg(sg, 3, SEQ*BAT, HID, bi2h, nullptr, 0, 0, s->U, s->Uh, s->Ul, BH, 1024);
    }
    // powers W^2 .. W^256 (squaring chain, tiled transposes)
    for (int k = 0; k < 8; k++) {
        k_transp<<<dim3(32,32), dim3(32,8)>>>(s->Th, s->Tl,
            k ? s->Wf[(k-1)&1] : Whh, k ? 1024 : 1536);
        const __half* Ah = k ? s->PWh[k-1] : s->W1h + 512;
        const __half* Al = k ? s->PWl[k-1] : s->W1l + 512;
        long long aI = k ? 1024 : 1536;
        TSeg sg[3] = { mkseg(Ah, 64*aI, aI, s->Th, 1024, 16),
                       mkseg(Al, 64*aI, aI, s->Th, 1024, 16),
                       mkseg(Ah, 64*aI, aI, s->Tl, 1024, 16) };
        tg(sg, 3, HID, HID, nullptr, nullptr, 0, 0, s->Wf[k&1], s->PWh[k], s->PWl[k], BH, 1024);
    }
    // block prefixes (L=8): p_{j,i+1} = p_{j,i} @ Whh^T + u_{8j+i}, i = 1..7, M = 4096
    int cur = 0;
    for (int i = 1; i <= 7; i++) {
        const __half* Ah = (i == 1) ? s->Uh : s->Ph[cur];
        const __half* Al = (i == 1) ? s->Ul : s->Pl[cur];
        long long aO = (i == 1) ? 8*BH : BH;
        TSeg sg[3] = { mkseg(Ah, aO, 1024, s->W1h + 512, 1536, 16),
                       mkseg(Al, aO, 1024, s->W1h + 512, 1536, 16),
                       mkseg(Ah, aO, 1024, s->W1l + 512, 1536, 16) };
        if (i < 7) {
            tg(sg, 3, 4096, HID, nullptr, s->U + (long long)i*BH, 8*BH, 1024,
               nullptr, s->Ph[cur^1], s->Pl[cur^1], BH, 1024);
            cur ^= 1;
        } else
            tg(sg, 3, 4096, HID, nullptr, s->U + (long long)i*BH, 8*BH, 1024,
               s->S[0] + BH, s->Sh[0] + BH, s->Sl[0] + BH, BH, 1024);
    }
    // Hillis-Steele boundary scan over 64 blocks: S[m] += S[m-g] @ (W^8g)^T, 6 levels
    k_zero3<<<64,1024>>>(s->S[0], s->Sh[0], s->Sl[0]);
    int a = 0;
    for (int d = 0; d < 6; d++) {
        const long long gp = 1LL << d;
        cudaMemcpyAsync(s->S[a^1],  s->S[a],  gp*BH*4, cudaMemcpyDeviceToDevice);
        cudaMemcpyAsync(s->Sh[a^1], s->Sh[a], gp*BH*2, cudaMemcpyDeviceToDevice);
        cudaMemcpyAsync(s->Sl[a^1], s->Sl[a], gp*BH*2, cudaMemcpyDeviceToDevice);
        TSeg sg[3] = { mkseg(s->Sh[a], BH, 1024, s->PWh[d+2], 1024, 16),
                       mkseg(s->Sl[a], BH, 1024, s->PWh[d+2], 1024, 16),
                       mkseg(s->Sh[a], BH, 1024, s->PWl[d+2], 1024, 16) };
        tg(sg, 3, (int)((65 - gp)*64), HID, nullptr, s->S[a] + gp*BH, BH, 1024,
           s->S[a^1] + gp*BH, s->Sh[a^1] + gp*BH, s->Sl[a^1] + gp*BH, BH, 1024);
        a ^= 1;
    }
    k_scatter<<<4160,1024>>>(s->Hh, s->Hl, s->Sh[a], s->Sl[a]);
    // refill: H[8j+i+1] = H[8j+i] @ Whh^T + u_{8j+i}, i = 0..6 (i=7 = boundaries)
    for (int i = 0; i < 7; i++) {
        const __half* Ah = (i == 0) ? s->Sh[a] : s->Hh + (long long)i*BH;
        const __half* Al = (i == 0) ? s->Sl[a] : s->Hl + (long long)i*BH;
        long long aO = (i == 0) ? BH : 8*BH;
        TSeg sg[3] = { mkseg(Ah, aO, 1024, s->W1h + 512, 1536, 16),
                       mkseg(Al, aO, 1024, s->W1h + 512, 1536, 16),
                       mkseg(Ah, aO, 1024, s->W1l + 512, 1536, 16) };
        tg(sg, 3, 4096, HID, nullptr, s->U + (long long)i*BH, 8*BH, 1024,
           nullptr, s->Hh + (long long)(i+1)*BH, s->Hl + (long long)(i+1)*BH, 8*BH, 1024);
    }
    // out = [x, h] @ Wi2o^T + b
    {
        TSeg sg[6] = { mkseg(s->xh, 32768, 512, s->W2h, 1536, 8),
                       mkseg(s->xl, 32768, 512, s->W2h, 1536, 8),
                       mkseg(s->xh, 32768, 512, s->W2l, 1536, 8),
                       mkseg(s->Hh, BH, 1024, s->W2h + 512, 1536, 16),
                       mkseg(s->Hl, BH, 1024, s->W2h + 512, 1536, 16),
                       mkseg(s->Hh, BH, 1024, s->W2l + 512, 1536, 16) };
        tg(sg, 6, SEQ*BAT, OUTD, bi2o, nullptr, 0, 0, nullptr, s->Oh, s->Ol, 32768, 512);
    }
    // oc = [out, h_next] @ Wo2o^T + b -> d_out
    {
        TSeg sg[6] = { mkseg(s->Oh, 32768, 512, s->W3h, 1536, 8),
                       mkseg(s->Ol, 32768, 512, s->W3h, 1536, 8),
                       mkseg(s->Oh, 32768, 512, s->W3l, 1536, 8),
                       mkseg(s->Hh + BH, BH, 1024, s->W3h + 512, 1536, 16),
                       mkseg(s->Hl + BH, BH, 1024, s->W3h + 512, 1536, 16),
                       mkseg(s->Hh + BH, BH, 1024, s->W3l + 512, 1536, 16) };
        tg(sg, 6, SEQ*BAT, OUTD, bo2o, nullptr, 0, 0, out, nullptr, nullptr, 32768, 512);
    }
    k_logsm<<<SEQ*BAT/8, 256>>>(out, mask);
}

// round 13
// speedup vs baseline: 1.9398x; 1.0313x over previous
#include <cuda_runtime.h>
#include <cuda_fp16.h>
#include <cstdint>

#define SEQ 512
#define BAT 64
#define HID 1024
#define OUTD 512
#define BH 65536LL   // BAT*HID

struct Scratch {
    float  U [SEQ*BAT*HID];
    __half Uh[SEQ*BAT*HID], Ul[SEQ*BAT*HID];
    __half Hh[(SEQ+1)*BAT*HID], Hl[(SEQ+1)*BAT*HID];
    __half Ph[2][4096*HID], Pl[2][4096*HID];
    float  S [2][65*BAT*HID];
    __half Sh[2][65*BAT*HID], Sl[2][65*BAT*HID];
    __half xh[SEQ*BAT*512], xl[SEQ*BAT*512];
    __half W1h[HID*1536],  W1l[HID*1536];
    __half W3h[OUTD*1536], W3l[OUTD*1536];
    float  Wf[2][HID*HID];
    __half Th[HID*HID], Tl[HID*HID];
    __half PWh[8][HID*HID], PWl[8][HID*HID];     // W^(2^(k+1)) hi/lo
    __half T2xh[512*512],  T2xl[512*512];        // (Wi2o x-block)^T
    __half T2hh[1024*512], T2hl[1024*512];       // (Wi2o h-block)^T
    __half Wc1h[512*512],  Wc1l[512*512];        // W3o @ W2x
    __half Wc2h[512*1024], Wc2l[512*1024];       // W3o @ W2h
    float  bc[512];
    float  part[4*1024*1024];                    // split-K partials
};
__device__ Scratch g;

// ---------------- PTX helpers (baseline PTX, sm_80+) ----------------
__device__ __forceinline__ uint32_t s2u(const void* p) {
    uint32_t a;
    asm("{ .reg .u64 t; cvta.to.shared.u64 t, %1; cvt.u32.u64 %0, t; }" : "=r"(a) : "l"(p));
    return a;
}
#define CP16(d,s) asm volatile("cp.async.cg.shared.global [%0], [%1], 16;" :: "r"(d), "l"(s) : "memory")
#define CPC() asm volatile("cp.async.commit_group;" ::: "memory")
#define CPW(n) asm volatile("cp.async.wait_group %0;" :: "n"(n) : "memory")
#define LDM4(r0,r1,r2,r3,a) \
    asm volatile("ldmatrix.sync.aligned.m8n8.x4.shared.b16 {%0,%1,%2,%3}, [%4];" \
        : "=r"(r0), "=r"(r1), "=r"(r2), "=r"(r3) : "r"(a))
#define MMA(d,a,b0,b1) \
    asm volatile("mma.sync.aligned.m16n8k16.row.col.f32.f16.f16.f32 " \
        "{%0,%1,%2,%3},{%4,%5,%6,%7},{%8,%9},{%0,%1,%2,%3};" \
        : "+f"((d)[0]), "+f"((d)[1]), "+f"((d)[2]), "+f"((d)[3]) \
        : "r"((a)[0]), "r"((a)[1]), "r"((a)[2]), "r"((a)[3]), "r"(b0), "r"(b1))

// ---------------- warp-MMA multi-segment GEMM (3-stage pipeline, split-K) ----------------
// C[r][n] = sum_seg sum_k A_s(r,k)*B_s(n,k) (+bias[n]) (+Add(r,n))
// row addr: (r>>6)*aO + (r&63)*aI ; B rows n are k-contiguous (stride wn).
// gridDim.z > 1: each z does zt ktiles, writes fp32 partial to part[z].
struct TSeg { const __half *A, *B; long long aO, aI, wn; int kt; };
struct TGP {
    TSeg s[9]; int ns, M, zt;
    const float *bias, *Add; long long adO, adI;
    float* C; __half *Chi, *Clo; long long cO, cI;   // C / Chi nullable
    float* part;
};
#define TG_SMEM 98304   // 3 stages x (16K A + 16K B)

__global__ __launch_bounds__(256) void k_tgemm(TGP p) {
    extern __shared__ char sm[];
    const uint32_t sb = s2u(sm);
    const int tid = threadIdx.x, lane = tid & 31, wid = tid >> 5;
    const int wm = wid & 3, wn = wid >> 2;          // 4 x 2 warp grid (32 x 64 tiles)
    const int mb = blockIdx.y * 128;
    const long long n0 = (long long)blockIdx.x * 128;
    const uint32_t BUF[3] = { sb, sb + 32768, sb + 65536 };
    const bool split = (gridDim.z > 1);

    const int rowp = tid >> 1;
    uint32_t lo[4];
    #pragma unroll
    for (int c = 0; c < 4; c++) {
        uint32_t o = rowp*128 + ((tid&1)*4 + c)*16;
        lo[c] = o ^ ((o >> 3) & 0x70);
    }
    int ma = mb + rowp; if (ma > p.M - 1) ma = p.M - 1;
    const long long nrow = n0 + rowp;

    int T = 0, ls = 0, lk = 0;
    if (split) {
        T = p.zt;
        int adv = blockIdx.z * p.zt;
        while (adv >= p.s[ls].kt) { adv -= p.s[ls].kt; ls++; }
        lk = adv;
    } else
        for (int s = 0; s < p.ns; s++) T += p.s[s].kt;

    auto load = [&](int buf) {
        const TSeg& sg = p.s[ls];
        const __half* a = sg.A + (long long)(ma>>6)*sg.aO + (long long)(ma&63)*sg.aI
                        + (long long)lk*64 + (tid&1)*32;
        const __half* b = sg.B + nrow*sg.wn + (long long)lk*64 + (tid&1)*32;
        #pragma unroll
        for (int c = 0; c < 4; c++) {
            CP16(BUF[buf] + lo[c], a + c*8);
            CP16(BUF[buf] + 16384 + lo[c], b + c*8);
        }
        CPC();
        if (++lk == sg.kt) { lk = 0; ls++; }
    };

    float acc[2][8][4];
    #pragma unroll
    for (int i = 0; i < 2; i++)
        #pragma unroll
        for (int j = 0; j < 8; j++)
            #pragma unroll
            for (int q = 0; q < 4; q++) acc[i][j][q] = 0.f;

    uint32_t arow[2], brow[4];
    #pragma unroll
    for (int mi = 0; mi < 2; mi++) arow[mi] = (uint32_t)(wm*32 + mi*16 + (lane & 15)) * 128;
    #pragma unroll
    for (int ni = 0; ni < 4; ni++) brow[ni] = (uint32_t)(wn*64 + ni*16 + (lane & 15)) * 128;
    const uint32_t kcol = (uint32_t)(lane >> 4) * 16;

    load(0);
    if (T > 1) load(1);
    for (int t = 0; t < T; t++) {
        if (t + 1 < T) CPW(1); else CPW(0);
        __syncthreads();
        if (t + 2 < T) load((t + 2) % 3);
        const uint32_t base = BUF[t % 3];
        #pragma unroll
        for (int ks = 0; ks < 4; ks++) {
            uint32_t af[2][4], bf[4][4];
            #pragma unroll
            for (int mi = 0; mi < 2; mi++) {
                uint32_t o = arow[mi] + ks*32 + kcol;
                o ^= (o >> 3) & 0x70;
                LDM4(af[mi][0], af[mi][1], af[mi][2], af[mi][3], base + o);
            }
            #pragma unroll
            for (int ni = 0; ni < 4; ni++) {
                uint32_t o = brow[ni] + ks*32 + kcol;
                o ^= (o >> 3) & 0x70;
                LDM4(bf[ni][0], bf[ni][1], bf[ni][2], bf[ni][3], base + 16384 + o);
            }
            #pragma unroll
            for (int mi = 0; mi < 2; mi++)
                #pragma unroll
                for (int gq = 0; gq < 4; gq++) {
                    MMA(acc[mi][2*gq],     af[mi], bf[gq][0], bf[gq][2]);
                    MMA(acc[mi][2*gq + 1], af[mi], bf[gq][1], bf[gq][3]);
                }
        }
    }

    // epilogue
    #pragma unroll
    for (int mi = 0; mi < 2; mi++)
        #pragma unroll
        for (int hh = 0; hh < 2; hh++) {
            const int row = mb + wm*32 + mi*16 + (lane >> 2) + hh*8;
            if (row >= p.M) continue;
            if (split) {
                const long long NN = (long long)gridDim.x * 128;
                float* P = p.part + (long long)blockIdx.z * p.M * NN + (long long)row * NN;
                #pragma unroll
                for (int nb = 0; nb < 8; nb++) {
                    const long long col = n0 + wn*64 + nb*8 + (lane & 3)*2;
                    *(float2*)(P + col) = make_float2(acc[mi][nb][hh*2], acc[mi][nb][hh*2+1]);
                }
            } else {
                const long long rb = (long long)(row>>6)*p.cO + (long long)(row&63)*p.cI;
                const long long ab = p.Add ? (long long)(row>>6)*p.adO + (long long)(row&63)*p.adI : 0;
                #pragma unroll
                for (int nb = 0; nb < 8; nb++) {
                    const long long col = n0 + wn*64 + nb*8 + (lane & 3)*2;
                    float v0 = acc[mi][nb][hh*2], v1 = acc[mi][nb][hh*2 + 1];
                    if (p.bias) { v0 += p.bias[col]; v1 += p.bias[col + 1]; }
                    if (p.Add) { float2 ad = *(const float2*)(p.Add + ab + col); v0 += ad.x; v1 += ad.y; }
                    if (p.C) *(float2*)(p.C + rb + col) = make_float2(v0, v1);
                    if (p.Chi) {
                        __half h0 = __float2half_rn(v0), h1 = __float2half_rn(v1);
                        *(__half2*)(p.Chi + rb + col) = __halves2half2(h0, h1);
                        *(__half2*)(p.Clo + rb + col) = __halves2half2(
                            __float2half_rn(v0 - __half2float(h0)),
                            __float2half_rn(v1 - __half2float(h1)));
                    }
                }
            }
        }
}

// ---------------- small kernels ----------------
__global__ void k_cvt(__half* h, __half* l, const float* s, int n) {
    int i = blockIdx.x*1024 + threadIdx.x;
    if (i < n) {
        float v = s[i];
        __half a = __float2half_rn(v);
        h[i] = a; l[i] = __float2half_rn(v - __half2float(a));
    }
}
// out[i][j] = src[j][i] (hi/lo halves); out is orows x ocols. grid(orows/32, ocols/32), block(32,8)
__global__ void k_transpG(__half* th, __half* tl, const float* src, int sstride, int ocols) {
    __shared__ float t[32][33];
    int tx = threadIdx.x, ty0 = threadIdx.y;
    int bi = blockIdx.x*32, bj = blockIdx.y*32;
    #pragma unroll
    for (int r = 0; r < 4; r++) {
        int ty = ty0*4 + r;
        t[ty][tx] = src[(long long)(bj+ty)*sstride + bi + tx];
    }
    __syncthreads();
    #pragma unroll
    for (int r = 0; r < 4; r++) {
        int row = ty0*4 + r;
        float v = t[tx][row];
        __half h = __float2half_rn(v);
        long long o = (long long)(bi+row)*ocols + bj + tx;
        th[o] = h; tl[o] = __float2half_rn(v - __half2float(h));
    }
}
// sum Z split-K partials; optional fp32 out + hi/lo halves
__global__ void k_red(float* f, __half* h, __half* l, const float* part, int cnt, int Z) {
    int i = blockIdx.x*1024 + threadIdx.x;
    if (i >= cnt) return;
    float s = part[i];
    for (int z = 1; z < Z; z++) s += part[(long long)z*cnt + i];
    if (f) f[i] = s;
    __half a = __float2half_rn(s);
    h[i] = a; l[i] = __float2half_rn(s - __half2float(a));
}
__global__ void k_biasfuse(float* bc, const float* b2, const float* b3, const float* W3) {
    int n = threadIdx.x;   // 512
    float s = b3[n];
    for (int j = 0; j < 512; j++) s += b2[j] * W3[n*1536 + j];
    bc[n] = s;
}
__global__ void k_zero3(float* f, __half* h, __half* l) {
    int i = blockIdx.x*1024 + threadIdx.x;
    f[i] = 0.f; h[i] = __half(0.f); l[i] = __half(0.f);
}
__global__ void k_scatter(__half* Hh, __half* Hl, const __half* Sh, const __half* Sl) {
    long long i = (long long)blockIdx.x*1024 + threadIdx.x;   // < 65*BH
    long long j = i >> 16, e = i & 65535;
    Hh[j*8*BH + e] = Sh[i];
    Hl[j*8*BH + e] = Sl[i];
}
__global__ void k_logsm(float* io, const float* mask) {
    int row = blockIdx.x*8 + (threadIdx.x >> 5), lane = threadIdx.x & 31;
    long long b = (long long)row*OUTD + lane;
    float v[16], mx = -1e30f;
    #pragma unroll
    for (int i = 0; i < 16; i++) { v[i] = io[b+32*i] * mask[b+32*i]; mx = fmaxf(mx, v[i]); }
    #pragma unroll
    for (int o = 16; o; o >>= 1) mx = fmaxf(mx, __shfl_xor_sync(~0u, mx, o));
    float s = 0.f;
    #pragma unroll
    for (int i = 0; i < 16; i++) s += expf(v[i] - mx);
    #pragma unroll
    for (int o = 16; o; o >>= 1) s += __shfl_xor_sync(~0u, s, o);
    float lse = mx + logf(s);
    #pragma unroll
    for (int i = 0; i < 16; i++) io[b+32*i] = v[i] - lse;
}

// ---------------- host ----------------
static TSeg mkseg(const __half* A, long long aO, long long aI,
                  const __half* B, long long wn, int kt) {
    TSeg t; t.A = A; t.aO = aO; t.aI = aI; t.B = B; t.wn = wn; t.kt = kt; return t;
}
static void tg(const TSeg* s, int ns, int M, int N, const float* bias,
               const float* Add, long long adO, long long adI,
               float* C, __half* Chi, __half* Clo, long long cO, long long cI,
               int Z = 1, int zt = 0, float* part = nullptr) {
    TGP p;
    for (int i = 0; i < ns; i++) p.s[i] = s[i];
    p.ns = ns; p.M = M; p.zt = zt; p.bias = bias; p.Add = Add; p.adO = adO; p.adI = adI;
    p.C = C; p.Chi = Chi; p.Clo = Clo; p.cO = cO; p.cI = cI; p.part = part;
    k_tgemm<<<dim3(N/128, (M+127)/128, Z), 256, TG_SMEM>>>(p);
}

extern "C" void kernel_launch(void* const* d_in, const int* in_sizes, int n_in,
                              void* d_out, int out_size)
{
    const float* x    = (const float*)d_in[0];
    const float* mask = (const float*)d_in[1];
    const float* Wi2h = (const float*)d_in[2];
    const float* bi2h = (const float*)d_in[3];
    const float* Wi2o = (const float*)d_in[4];
    const float* bi2o = (const float*)d_in[5];
    const float* Wo2o = (const float*)d_in[6];
    const float* bo2o = (const float*)d_in[7];
    float* out = (float*)d_out;
    (void)in_sizes; (void)n_in; (void)out_size;

    cudaFuncSetAttribute(k_tgemm, cudaFuncAttributeMaxDynamicSharedMemorySize, TG_SMEM);
    Scratch* s; cudaGetSymbolAddress((void**)&s, g);
    const float* Whh = Wi2h + 512;

    // converts
    k_cvt<<<16384,1024>>>(s->xh, s->xl, x, SEQ*BAT*512);
    k_cvt<<<1536,1024>>>(s->W1h, s->W1l, Wi2h, HID*1536);
    k_cvt<<<768,1024>>>(s->W3h, s->W3l, Wo2o, OUTD*1536);

    // ---- fused output weights: Wc1 = W3o@W2x, Wc2 = W3o@W2h, bc = b3 + b2@W3o^T
    k_transpG<<<dim3(16,16), dim3(32,8)>>>(s->T2xh, s->T2xl, Wi2o, 1536, 512);
    k_transpG<<<dim3(32,16), dim3(32,8)>>>(s->T2hh, s->T2hl, Wi2o + 512, 1536, 512);
    {
        TSeg sg[3] = { mkseg(s->W3h, 64*1536, 1536, s->T2xh, 512, 8),
                       mkseg(s->W3l, 64*1536, 1536, s->T2xh, 512, 8),
                       mkseg(s->W3h, 64*1536, 1536, s->T2xl, 512, 8) };
        tg(sg, 3, 512, 512, nullptr, nullptr, 0, 0, nullptr, nullptr, nullptr, 0, 0,
           3, 8, s->part);
        k_red<<<256,1024>>>(nullptr, s->Wc1h, s->Wc1l, s->part, 512*512, 3);
    }
    {
        TSeg sg[3] = { mkseg(s->W3h, 64*1536, 1536, s->T2hh, 512, 8),
                       mkseg(s->W3l, 64*1536, 1536, s->T2hh, 512, 8),
                       mkseg(s->W3h, 64*1536, 1536, s->T2hl, 512, 8) };
        tg(sg, 3, 512, 1024, nullptr, nullptr, 0, 0, nullptr, nullptr, nullptr, 0, 0,
           3, 8, s->part);
        k_red<<<512,1024>>>(nullptr, s->Wc2h, s->Wc2l, s->part, 512*1024, 3);
    }
    k_biasfuse<<<1,512>>>(s->bc, bi2o, bo2o, Wo2o);

    // U = x @ Wxh^T + b
    {
        TSeg sg[3] = { mkseg(s->xh, 32768, 512, s->W1h, 1536, 8),
                       mkseg(s->xl, 32768, 512, s->W1h, 1536, 8),
                       mkseg(s->xh, 32768, 512, s->W1l, 1536, 8) };
        tg(sg, 3, SEQ*BAT, HID, bi2h, nullptr, 0, 0, s->U, s->Uh, s->Ul, BH, 1024);
    }
    // powers W^2 .. W^256 (squaring chain, split-K x4)
    for (int k = 0; k < 8; k++) {
        k_transpG<<<dim3(32,32), dim3(32,8)>>>(s->Th, s->Tl,
            k ? s->Wf[(k-1)&1] : Whh, k ? 1024 : 1536, 1024);
        const __half* Ah = k ? s->PWh[k-1] : s->W1h + 512;
        const __half* Al = k ? s->PWl[k-1] : s->W1l + 512;
        long long aI = k ? 1024 : 1536;
        TSeg sg[3] = { mkseg(Ah, 64*aI, aI, s->Th, 1024, 16),
                       mkseg(Al, 64*aI, aI, s->Th, 1024, 16),
                       mkseg(Ah, 64*aI, aI, s->Tl, 1024, 16) };
        tg(sg, 3, HID, HID, nullptr, nullptr, 0, 0, nullptr, nullptr, nullptr, 0, 0,
           4, 12, s->part);
        k_red<<<1024,1024>>>(s->Wf[k&1], s->PWh[k], s->PWl[k], s->part, 1024*1024, 4);
    }
    // block prefixes (L=8): p_{j,i+1} = p_{j,i} @ Whh^T + u_{8j+i}, i = 1..7, M = 4096
    int cur = 0;
    for (int i = 1; i <= 7; i++) {
        const __half* Ah = (i == 1) ? s->Uh : s->Ph[cur];
        const __half* Al = (i == 1) ? s->Ul : s->Pl[cur];
        long long aO = (i == 1) ? 8*BH : BH;
        TSeg sg[3] = { mkseg(Ah, aO, 1024, s->W1h + 512, 1536, 16),
                       mkseg(Al, aO, 1024, s->W1h + 512, 1536, 16),
                       mkseg(Ah, aO, 1024, s->W1l + 512, 1536, 16) };
        if (i < 7) {
            tg(sg, 3, 4096, HID, nullptr, s->U + (long long)i*BH, 8*BH, 1024,
               nullptr, s->Ph[cur^1], s->Pl[cur^1], BH, 1024);
            cur ^= 1;
        } else
            tg(sg, 3, 4096, HID, nullptr, s->U + (long long)i*BH, 8*BH, 1024,
               s->S[0] + BH, s->Sh[0] + BH, s->Sl[0] + BH, BH, 1024);
    }
    // Hillis-Steele boundary scan over 64 blocks: S[m] += S[m-g] @ (W^8g)^T, 6 levels
    k_zero3<<<64,1024>>>(s->S[0], s->Sh[0], s->Sl[0]);
    int a = 0;
    for (int d = 0; d < 6; d++) {
        const long long gp = 1LL << d;
        cudaMemcpyAsync(s->S[a^1],  s->S[a],  gp*BH*4, cudaMemcpyDeviceToDevice);
        cudaMemcpyAsync(s->Sh[a^1], s->Sh[a], gp*BH*2, cudaMemcpyDeviceToDevice);
        cudaMemcpyAsync(s->Sl[a^1], s->Sl[a], gp*BH*2, cudaMemcpyDeviceToDevice);
        TSeg sg[3] = { mkseg(s->Sh[a], BH, 1024, s->PWh[d+2], 1024, 16),
                       mkseg(s->Sl[a], BH, 1024, s->PWh[d+2], 1024, 16),
                       mkseg(s->Sh[a], BH, 1024, s->PWl[d+2], 1024, 16) };
        tg(sg, 3, (int)((65 - gp)*64), HID, nullptr, s->S[a] + gp*BH, BH, 1024,
           s->S[a^1] + gp*BH, s->Sh[a^1] + gp*BH, s->Sl[a^1] + gp*BH, BH, 1024);
        a ^= 1;
    }
    k_scatter<<<4160,1024>>>(s->Hh, s->Hl, s->Sh[a], s->Sl[a]);
    // refill: H[8j+i+1] = H[8j+i] @ Whh^T + u_{8j+i}, i = 0..6 (i=7 = boundaries)
    for (int i = 0; i < 7; i++) {
        const __half* Ah = (i == 0) ? s->Sh[a] : s->Hh + (long long)i*BH;
        const __half* Al = (i == 0) ? s->Sl[a] : s->Hl + (long long)i*BH;
        long long aO = (i == 0) ? BH : 8*BH;
        TSeg sg[3] = { mkseg(Ah, aO, 1024, s->W1h + 512, 1536, 16),
                       mkseg(Al, aO, 1024, s->W1h + 512, 1536, 16),
                       mkseg(Ah, aO, 1024, s->W1l + 512, 1536, 16) };
        tg(sg, 3, 4096, HID, nullptr, s->U + (long long)i*BH, 8*BH, 1024,
           nullptr, s->Hh + (long long)(i+1)*BH, s->Hl + (long long)(i+1)*BH, 8*BH, 1024);
    }
    // oc = x@Wc1^T + h@Wc2^T + h'@W3h^T + bc  (single fused launch, 9 segments)
    {
        TSeg sg[9] = { mkseg(s->xh, 32768, 512, s->Wc1h, 512, 8),
                       mkseg(s->xl, 32768, 512, s->Wc1h, 512, 8),
                       mkseg(s->xh, 32768, 512, s->Wc1l, 512, 8),
                       mkseg(s->Hh, BH, 1024, s->Wc2h, 1024, 16),
                       mkseg(s->Hl, BH, 1024, s->Wc2h, 1024, 16),
                       mkseg(s->Hh, BH, 1024, s->Wc2l, 1024, 16),
                       mkseg(s->Hh + BH, BH, 1024, s->W3h + 512, 1536, 16),
                       mkseg(s->Hl + BH, BH, 1024, s->W3h + 512, 1536, 16),
                       mkseg(s->Hh + BH, BH, 1024, s->W3l + 512, 1536, 16) };
        tg(sg, 9, SEQ*BAT, OUTD, s->bc, nullptr, 0, 0, out, nullptr, nullptr, 32768, 512);
    }
    k_logsm<<<SEQ*BAT/8, 256>>>(out, mask);
}